// round 14
// baseline (speedup 1.0000x reference)
#include <cuda_runtime.h>

// HBilinearUpsample: Poincare-ball geodesic bilinear upsample (c = 1).
// midpoint(x,y) = P*x + Q*y with (P,Q) from Gram scalars only;
// tanh(atanh(z)/2) = z/(1+sqrt(1-z^2)) -> no transcendentals.
//
// Fused kernel, 2 row-pairs per block (3 staged rows -> 4 output rows):
//   stage rows 0,1 -> [gram(pair0) || stage row2] -> coeffs(0)
//   -> [write(pair0) || gram(pair1)] -> coeffs(1) -> write(pair1)
// smem tile uses a 16-float XOR swizzle for conflict-free column reads.

static constexpr int B  = 8;
static constexpr int C  = 64;
static constexpr int H  = 128;
static constexpr int W  = 128;
static constexpr int HW = H * W;
static constexpr int CHW = C * HW;
static constexpr int Ho = 2 * H;
static constexpr int Wo = 2 * W;
static constexpr int HoWo = Ho * Wo;

static constexpr int SMEM_TILE_BYTES = 3 * C * W * 4;   // 98304

#define EPS_F  1e-15f
#define MAXA_F 0.99999f   // 1 - 1e-5

// ---------------------------------------------------------------------------
// midpoint(x,y) = P*x + Q*y given (|x|^2, |y|^2, <x,y>), c = 1.
// Mirrors the reference clip chain.
// ---------------------------------------------------------------------------
__device__ __forceinline__ void mid_coeffs(float x2, float y2, float xy,
                                           float& P, float& Q) {
    float den1 = fmaxf(1.f - 2.f * xy + x2 * y2, EPS_F);
    float inv1 = __fdividef(1.f, den1);
    float A  = -(1.f - 2.f * xy + y2) * inv1;
    float Bc = (1.f - x2) * inv1;
    float w2 = A * A * x2 + 2.f * A * Bc * xy + Bc * Bc * y2;
    float wn = sqrtf(fmaxf(w2, EPS_F));
    float wc = fminf(wn, MAXA_F);
    float tau = __fdividef(wc, wn * (1.f + sqrtf(fmaxf(1.f - wc * wc, 0.f))));
    float Sa = tau * A;
    float Sb = tau * Bc;
    float xs = tau * (A * x2 + Bc * xy);
    float s2 = tau * tau * w2;
    float k = 1.f + 2.f * xs + s2;
    float den2 = fmaxf(1.f + 2.f * xs + x2 * s2, EPS_F);
    float inv2 = __fdividef(1.f, den2);
    P = (k + (1.f - x2) * Sa) * inv2;
    Q = (1.f - x2) * Sb * inv2;
}

// ---------------------------------------------------------------------------
// Fused kernel. 512 threads; grid (H/2, B).
// smem tile: s[(r*64+c)*128 + (w ^ 8*(c&3))], r in {0,1,2} = rows h0,h0+1,h0+2.
// ---------------------------------------------------------------------------
__global__ void __launch_bounds__(512) fused_kernel(const float* __restrict__ x,
                                                    float* __restrict__ out) {
    extern __shared__ float s[];
    __shared__ float  fin[7][W];
    __shared__ __align__(16) float2 sca2[W][2];  // [w][0]=(Pa,Qa) [w][1]=(Pv,Qv)
    __shared__ float4 scb[W];                    // C00,C10,C01,C11
    __shared__ float2 spqb[W];                   // (Pb,Qb) handoff

    const int tid = threadIdx.x;
    const int h0  = 2 * blockIdx.x;
    const int b   = blockIdx.y;
    const float* xb = x + b * CHW;

    // ---- Gram accumulation for pair p (rows p, p+1 of the tile) ----
    auto gram = [&](int p) {
        const int lane = tid & 31;
        const int wp   = tid >> 5;        // warp 0..15
        const int dw   = lane >> 2;       // cell within warp 0..7
        const int cg   = lane & 3;        // channel group 0..3
        const int w    = wp * 8 + dw;
        const int w1   = min(w + 1, W - 1);
        const int m    = cg * 8;
        const int o_u  = (w  ^ m);
        const int o_e  = (w1 ^ m);
        const float* t0 = s + (p * C) * W;
        const float* t1 = s + ((p + 1) * C) * W;

        float nA=0, nB=0, hA=0, hB=0, vv=0, gg=0, aa=0;
#pragma unroll 4
        for (int i = 0; i < 16; i++) {
            const int c = 4 * i + cg;     // c & 3 == cg -> swizzle m matches
            const float* r0 = t0 + c * W;
            const float* r1 = t1 + c * W;
            float u  = r0[o_u];
            float eu = r0[o_e];
            float d  = r1[o_u];
            float ed = r1[o_e];
            nA = fmaf(u,  u,  nA);
            nB = fmaf(d,  d,  nB);
            hA = fmaf(u,  eu, hA);
            hB = fmaf(d,  ed, hB);
            vv = fmaf(u,  d,  vv);
            gg = fmaf(u,  ed, gg);
            aa = fmaf(eu, d,  aa);
        }
#define RED4(v) v += __shfl_xor_sync(0xffffffffu, v, 1); \
                v += __shfl_xor_sync(0xffffffffu, v, 2);
        RED4(nA) RED4(nB) RED4(hA) RED4(hB) RED4(vv) RED4(gg) RED4(aa)
#undef RED4
        if (cg == 0) {
            fin[0][w] = nA;
            fin[1][w] = nB;
            fin[2][w] = hA;
            fin[3][w] = hB;
            fin[4][w] = vv;
            fin[5][w] = gg;
            fin[6][w] = aa;
        }
    };

    // ---- Phase 2a: three independent midpoints on 384 threads ----
    auto coeff_a = [&]() {
        const int g = tid >> 7;           // 0..3
        const int w = tid & 127;
        const int w1 = min(w + 1, W - 1);
        if (g == 0) {                     // a = mid(x00, x10)
            float P, Q;
            mid_coeffs(fin[0][w], fin[0][w1], fin[2][w], P, Q);
            sca2[w][0] = make_float2(P, Q);
        } else if (g == 1) {              // mid_v = mid(x00, x01)
            float P, Q;
            mid_coeffs(fin[0][w], fin[1][w], fin[4][w], P, Q);
            sca2[w][1] = make_float2(P, Q);
        } else if (g == 2) {              // b = mid(x01, x11)
            float P, Q;
            mid_coeffs(fin[1][w], fin[1][w1], fin[3][w], P, Q);
            spqb[w] = make_float2(P, Q);
        }
    };

    // ---- Phase 2b: center midpoint + combine (128 threads) ----
    auto coeff_b = [&]() {
        if (tid < W) {
            const int w  = tid;
            const int w1 = min(w + 1, W - 1);
            const float2 pa = sca2[w][0];
            const float2 pb = spqb[w];
            const float n00 = fin[0][w], n10 = fin[0][w1];
            const float n01 = fin[1][w], n11 = fin[1][w1];
            const float dhT = fin[2][w], dhB = fin[3][w];
            const float dvL = fin[4][w], dvR = fin[4][w1];
            const float dgd = fin[5][w], dad = fin[6][w];

            float a2 = pa.x * pa.x * n00 + 2.f * pa.x * pa.y * dhT + pa.y * pa.y * n10;
            float b2 = pb.x * pb.x * n01 + 2.f * pb.x * pb.y * dhB + pb.y * pb.y * n11;
            float ab = pa.x * pb.x * dvL + pa.x * pb.y * dgd
                     + pa.y * pb.x * dad + pa.y * pb.y * dvR;
            float Pc, Qc;
            mid_coeffs(a2, b2, ab, Pc, Qc);
            scb[w] = make_float4(Pc * pa.x, Pc * pa.y, Qc * pb.x, Qc * pb.y);
        }
    };

    // ---- Phase 3: write both output rows for pair p (STG.128 streaming) ----
    auto writeout = [&](int p) {
        const int lw = tid & 63;
        const int cg = tid >> 6;          // channel group 0..7
        const int w0 = 2 * lw;
        const int w2 = min(w0 + 2, W - 1);

        const float4 k0a = *reinterpret_cast<const float4*>(&sca2[w0][0]);
        const float4 k1a = *reinterpret_cast<const float4*>(&sca2[w0 + 1][0]);
        const float4 k0b = scb[w0];
        const float4 k1b = scb[w0 + 1];

        const float* t0 = s + (p * C) * W;
        const float* t1 = s + ((p + 1) * C) * W;
        float* po = out + (size_t)b * C * HoWo + (size_t)cg * 8 * HoWo
                        + (2 * (h0 + p)) * Wo + 4 * lw;

#pragma unroll 2
        for (int i = 0; i < 8; i++) {
            const int c = cg * 8 + i;
            const int m = (c & 3) * 8;
            const float* r0 = t0 + c * W;
            const float* r1 = t1 + c * W;
            float2 u = *reinterpret_cast<const float2*>(&r0[w0 ^ m]);
            float eu = r0[w2 ^ m];
            float2 d = *reinterpret_cast<const float2*>(&r1[w0 ^ m]);
            float ed = r1[w2 ^ m];

            float4 top, bot;
            top.x = u.x;
            top.y = fmaf(k0a.x, u.x, k0a.y * u.y);
            top.z = u.y;
            top.w = fmaf(k1a.x, u.y, k1a.y * eu);
            bot.x = fmaf(k0a.z, u.x, k0a.w * d.x);
            bot.y = fmaf(k0b.x, u.x, fmaf(k0b.y, u.y, fmaf(k0b.z, d.x, k0b.w * d.y)));
            bot.z = fmaf(k1a.z, u.y, k1a.w * d.y);
            bot.w = fmaf(k1b.x, u.y, fmaf(k1b.y, eu, fmaf(k1b.z, d.y, k1b.w * ed)));

            float* pc = po + (size_t)i * HoWo;
            __stcs(reinterpret_cast<float4*>(pc), top);
            __stcs(reinterpret_cast<float4*>(pc + Wo), bot);
        }
    };

    // ==== Schedule ====
    // Stage rows 0,1 (coalesced LDG.128 -> swizzled smem)
    {
        const int row_off[2] = { h0 * W, (h0 + 1) * W };
#pragma unroll
        for (int k = 0; k < 8; k++) {
            const int i  = tid + k * 512;
            const int j  = (i & 31) * 4;
            const int rc = i >> 5;            // 0..127
            const int c  = rc & 63;
            const int r  = rc >> 6;
            const int m  = (c & 3) * 8;
            float4 v = *reinterpret_cast<const float4*>(xb + c * HW + row_off[r] + j);
            *reinterpret_cast<float4*>(&s[rc * W + (j ^ m)]) = v;
        }
    }
    __syncthreads();

    // Gram(pair0) overlapped with staging of row 2
    {
        const int row2 = min(h0 + 2, H - 1) * W;
#pragma unroll
        for (int k = 0; k < 4; k++) {
            const int i = tid + k * 512;
            const int j = (i & 31) * 4;
            const int c = i >> 5;             // 0..63
            const int m = (c & 3) * 8;
            float4 v = *reinterpret_cast<const float4*>(xb + c * HW + row2 + j);
            *reinterpret_cast<float4*>(&s[(2 * C + c) * W + (j ^ m)]) = v;
        }
    }
    gram(0);
    __syncthreads();

    coeff_a();
    __syncthreads();
    coeff_b();
    __syncthreads();

    // Write(pair0) overlapped with Gram(pair1)
    writeout(0);
    gram(1);
    __syncthreads();

    coeff_a();
    __syncthreads();
    coeff_b();
    __syncthreads();

    writeout(1);
}

extern "C" void kernel_launch(void* const* d_in, const int* in_sizes, int n_in,
                              void* d_out, int out_size) {
    const float* x = (const float*)d_in[0];
    float* out = (float*)d_out;
    (void)in_sizes; (void)n_in; (void)out_size;

    cudaFuncSetAttribute(fused_kernel,
                         cudaFuncAttributeMaxDynamicSharedMemorySize,
                         SMEM_TILE_BYTES);
    fused_kernel<<<dim3(H / 2, B), 512, SMEM_TILE_BYTES>>>(x, out);
}

// round 15
// speedup vs baseline: 1.1713x; 1.1713x over previous
#include <cuda_runtime.h>
#include <cstdint>

// HBilinearUpsample: Poincare-ball geodesic bilinear upsample (c = 1).
// midpoint(x,y) = P*x + Q*y with (P,Q) from Gram scalars only;
// tanh(atanh(z)/2) = z/(1+sqrt(1-z^2)) -> no transcendentals.
//
// Fused single kernel (R13 structure: 1 row-pair/block, 64KB tile, 3 blk/SM):
//   Phase 0: cp.async staging, rows h and h+1 in separate commit groups
//   Phase 1a: after wait_group 1 (row h ready): nA,hA fields (overlaps row h1)
//   Phase 1b: after wait_group 0: nB,hB,vv,gg,aa fields; shfl_xor reduce
//   Phase 2: 3 independent midpoints on 384 threads, then center on 128
//   Phase 3: all 16 warps emit both output rows with STG.128 streaming

static constexpr int B  = 8;
static constexpr int C  = 64;
static constexpr int H  = 128;
static constexpr int W  = 128;
static constexpr int HW = H * W;
static constexpr int CHW = C * HW;
static constexpr int Ho = 2 * H;
static constexpr int Wo = 2 * W;
static constexpr int HoWo = Ho * Wo;

static constexpr int SMEM_TILE_BYTES = 2 * C * W * 4;   // 65536

#define EPS_F  1e-15f
#define MAXA_F 0.99999f   // 1 - 1e-5

// ---------------------------------------------------------------------------
// midpoint(x,y) = P*x + Q*y given (|x|^2, |y|^2, <x,y>), c = 1.
// Mirrors the reference clip chain.
// ---------------------------------------------------------------------------
__device__ __forceinline__ void mid_coeffs(float x2, float y2, float xy,
                                           float& P, float& Q) {
    float den1 = fmaxf(1.f - 2.f * xy + x2 * y2, EPS_F);
    float inv1 = __fdividef(1.f, den1);
    float A  = -(1.f - 2.f * xy + y2) * inv1;
    float Bc = (1.f - x2) * inv1;
    float w2 = A * A * x2 + 2.f * A * Bc * xy + Bc * Bc * y2;
    float wn = sqrtf(fmaxf(w2, EPS_F));
    float wc = fminf(wn, MAXA_F);
    float tau = __fdividef(wc, wn * (1.f + sqrtf(fmaxf(1.f - wc * wc, 0.f))));
    float Sa = tau * A;
    float Sb = tau * Bc;
    float xs = tau * (A * x2 + Bc * xy);
    float s2 = tau * tau * w2;
    float k = 1.f + 2.f * xs + s2;
    float den2 = fmaxf(1.f + 2.f * xs + x2 * s2, EPS_F);
    float inv2 = __fdividef(1.f, den2);
    P = (k + (1.f - x2) * Sa) * inv2;
    Q = (1.f - x2) * Sb * inv2;
}

// ---------------------------------------------------------------------------
// Fused kernel. 512 threads; grid (H, B).
// smem tile: s[rc*128 + (w ^ 8*(c&3))], rc = r*64+c, r in {0,1} rows {h,h1}.
// ---------------------------------------------------------------------------
__global__ void __launch_bounds__(512) fused_kernel(const float* __restrict__ x,
                                                    float* __restrict__ out) {
    extern __shared__ float s[];
    __shared__ float  fin[7][W];
    __shared__ __align__(16) float2 sca2[W][2];  // [w][0]=(Pa,Qa) [w][1]=(Pv,Qv)
    __shared__ float4 scb[W];                    // C00,C10,C01,C11
    __shared__ float2 spqb[W];                   // (Pb,Qb) handoff

    const int tid = threadIdx.x;
    const int h   = blockIdx.x;
    const int b   = blockIdx.y;
    const int h1  = min(h + 1, H - 1);
    const float* xb = x + b * CHW;

    // ---- Phase 0: cp.async staging, two commit groups (row h, row h1) ----
    const uint32_t sb = (uint32_t)__cvta_generic_to_shared(s);
    {
#pragma unroll
        for (int k = 0; k < 4; k++) {            // row h -> tile rows 0..63
            const int i = tid + k * 512;         // float4 idx 0..2047
            const int j = (i & 31) * 4;
            const int c = i >> 5;                // 0..63
            const int m = (c & 3) * 8;
            const uint32_t dst = sb + (uint32_t)((c * W + (j ^ m)) * 4);
            const float* src = xb + c * HW + h * W + j;
            asm volatile("cp.async.cg.shared.global [%0], [%1], 16;\n"
                         :: "r"(dst), "l"(src));
        }
        asm volatile("cp.async.commit_group;\n" ::: "memory");
#pragma unroll
        for (int k = 0; k < 4; k++) {            // row h1 -> tile rows 64..127
            const int i = tid + k * 512;
            const int j = (i & 31) * 4;
            const int c = i >> 5;
            const int m = (c & 3) * 8;
            const uint32_t dst = sb + (uint32_t)(((C + c) * W + (j ^ m)) * 4);
            const float* src = xb + c * HW + h1 * W + j;
            asm volatile("cp.async.cg.shared.global [%0], [%1], 16;\n"
                         :: "r"(dst), "l"(src));
        }
        asm volatile("cp.async.commit_group;\n" ::: "memory");
    }

    // Lane geometry (shared by both gram passes)
    const int lane = tid & 31;
    const int wp   = tid >> 5;        // warp 0..15
    const int dw   = lane >> 2;       // cell within warp 0..7
    const int cg   = lane & 3;        // channel group 0..3
    const int w    = wp * 8 + dw;
    const int w1   = min(w + 1, W - 1);
    const int mm   = cg * 8;
    const int o_u  = (w  ^ mm);
    const int o_e  = (w1 ^ mm);

#define RED4(v) v += __shfl_xor_sync(0xffffffffu, v, 1); \
                v += __shfl_xor_sync(0xffffffffu, v, 2);

    // ---- Phase 1a: row-h-only fields (overlaps row h1 in flight) ----
    asm volatile("cp.async.wait_group 1;\n" ::: "memory");
    __syncthreads();
    {
        float nA = 0.f, hA = 0.f;
#pragma unroll 4
        for (int i = 0; i < 16; i++) {
            const int c = 4 * i + cg;
            const float* r0 = s + c * W;
            float u  = r0[o_u];
            float eu = r0[o_e];
            nA = fmaf(u, u,  nA);
            hA = fmaf(u, eu, hA);
        }
        RED4(nA) RED4(hA)
        if (cg == 0) {
            fin[0][w] = nA;
            fin[2][w] = hA;
        }
    }

    // ---- Phase 1b: remaining fields (needs row h1) ----
    asm volatile("cp.async.wait_group 0;\n" ::: "memory");
    __syncthreads();
    {
        float nB=0, hB=0, vv=0, gg=0, aa=0;
#pragma unroll 4
        for (int i = 0; i < 16; i++) {
            const int c = 4 * i + cg;
            const float* r0 = s + c * W;
            const float* r1 = s + (C + c) * W;
            float u  = r0[o_u];
            float eu = r0[o_e];
            float d  = r1[o_u];
            float ed = r1[o_e];
            nB = fmaf(d,  d,  nB);
            hB = fmaf(d,  ed, hB);
            vv = fmaf(u,  d,  vv);
            gg = fmaf(u,  ed, gg);
            aa = fmaf(eu, d,  aa);
        }
        RED4(nB) RED4(hB) RED4(vv) RED4(gg) RED4(aa)
        if (cg == 0) {
            fin[1][w] = nB;
            fin[3][w] = hB;
            fin[4][w] = vv;
            fin[5][w] = gg;
            fin[6][w] = aa;
        }
    }
#undef RED4
    __syncthreads();

    // ---- Phase 2a: three independent midpoints on 384 threads ----
    {
        const int g = tid >> 7;           // 0..3
        const int ww = tid & 127;
        const int ww1 = min(ww + 1, W - 1);
        if (g == 0) {                     // a = mid(x00, x10)
            float P, Q;
            mid_coeffs(fin[0][ww], fin[0][ww1], fin[2][ww], P, Q);
            sca2[ww][0] = make_float2(P, Q);
        } else if (g == 1) {              // mid_v = mid(x00, x01)
            float P, Q;
            mid_coeffs(fin[0][ww], fin[1][ww], fin[4][ww], P, Q);
            sca2[ww][1] = make_float2(P, Q);
        } else if (g == 2) {              // b = mid(x01, x11)
            float P, Q;
            mid_coeffs(fin[1][ww], fin[1][ww1], fin[3][ww], P, Q);
            spqb[ww] = make_float2(P, Q);
        }
    }
    __syncthreads();

    // ---- Phase 2b: center midpoint + combine (128 threads) ----
    if (tid < W) {
        const int ww  = tid;
        const int ww1 = min(ww + 1, W - 1);

        const float2 pa = sca2[ww][0];    // Pa, Qa
        const float2 pb = spqb[ww];       // Pb, Qb
        const float n00 = fin[0][ww], n10 = fin[0][ww1];
        const float n01 = fin[1][ww], n11 = fin[1][ww1];
        const float dhT = fin[2][ww], dhB = fin[3][ww];
        const float dvL = fin[4][ww], dvR = fin[4][ww1];
        const float dgd = fin[5][ww], dad = fin[6][ww];

        float a2 = pa.x * pa.x * n00 + 2.f * pa.x * pa.y * dhT + pa.y * pa.y * n10;
        float b2 = pb.x * pb.x * n01 + 2.f * pb.x * pb.y * dhB + pb.y * pb.y * n11;
        float ab = pa.x * pb.x * dvL + pa.x * pb.y * dgd
                 + pa.y * pb.x * dad + pa.y * pb.y * dvR;
        float Pc, Qc;
        mid_coeffs(a2, b2, ab, Pc, Qc);   // center = mid(a, b)

        scb[ww] = make_float4(Pc * pa.x, Pc * pa.y, Qc * pb.x, Qc * pb.y);
    }
    __syncthreads();

    // ---- Phase 3: write both output rows (all 16 warps, STG.128) ----
    const int lw = tid & 63;      // 2-cell column group: w0 = 2*lw
    const int cgr = tid >> 6;     // channel group 0..7 (8 channels each)
    const int w0 = 2 * lw;
    const int w2 = min(w0 + 2, W - 1);

    const float4 k0a = *reinterpret_cast<const float4*>(&sca2[w0][0]);
    const float4 k1a = *reinterpret_cast<const float4*>(&sca2[w0 + 1][0]);
    const float4 k0b = scb[w0];
    const float4 k1b = scb[w0 + 1];

    float* po = out + (size_t)b * C * HoWo + (size_t)cgr * 8 * HoWo
                    + (2 * h) * Wo + 4 * lw;

#pragma unroll 2
    for (int i = 0; i < 8; i++) {
        const int c = cgr * 8 + i;
        const int m = (c & 3) * 8;
        const float* r0 = s + c * W;
        const float* r1 = s + (C + c) * W;
        float2 u = *reinterpret_cast<const float2*>(&r0[w0 ^ m]);
        float eu = r0[w2 ^ m];
        float2 d = *reinterpret_cast<const float2*>(&r1[w0 ^ m]);
        float ed = r1[w2 ^ m];

        float4 top, bot;
        top.x = u.x;
        top.y = fmaf(k0a.x, u.x, k0a.y * u.y);
        top.z = u.y;
        top.w = fmaf(k1a.x, u.y, k1a.y * eu);
        bot.x = fmaf(k0a.z, u.x, k0a.w * d.x);
        bot.y = fmaf(k0b.x, u.x, fmaf(k0b.y, u.y, fmaf(k0b.z, d.x, k0b.w * d.y)));
        bot.z = fmaf(k1a.z, u.y, k1a.w * d.y);
        bot.w = fmaf(k1b.x, u.y, fmaf(k1b.y, eu, fmaf(k1b.z, d.y, k1b.w * ed)));

        float* pc = po + (size_t)i * HoWo;
        __stcs(reinterpret_cast<float4*>(pc), top);
        __stcs(reinterpret_cast<float4*>(pc + Wo), bot);
    }
}

extern "C" void kernel_launch(void* const* d_in, const int* in_sizes, int n_in,
                              void* d_out, int out_size) {
    const float* x = (const float*)d_in[0];
    float* out = (float*)d_out;
    (void)in_sizes; (void)n_in; (void)out_size;

    cudaFuncSetAttribute(fused_kernel,
                         cudaFuncAttributeMaxDynamicSharedMemorySize,
                         SMEM_TILE_BYTES);
    fused_kernel<<<dim3(H, B), 512, SMEM_TILE_BYTES>>>(x, out);
}